// round 1
// baseline (speedup 1.0000x reference)
#include <cuda_runtime.h>

#define NTOK 4096
#define DMODEL 256
#define NHEAD 8
#define HEADD 32
#define KDIM 256
#define SCALE 0.17677669529663689f

// Scratch (device globals — no allocation allowed in kernel_launch)
__device__ float g_qkv[NTOK * 3 * DMODEL];   // [n][c*256 + h*32 + d], c in {q,k,v}
__device__ float g_pe[NHEAD * NTOK];         // [h][n] = pe @ Wpe + bpe
__device__ float g_att[NTOK * DMODEL];       // [n][h*32+d]

// ---------------------------------------------------------------------------
// Generic tiled SGEMM: C[M,Nc] = A[M,256] @ B[256,Nc] + bias[Nc]
// 64x64 tile, BK=16, 256 threads, 4x4 microtile per thread.
// ---------------------------------------------------------------------------
__global__ __launch_bounds__(256) void gemm_bias_kernel(
    const float* __restrict__ A, const float* __restrict__ B,
    const float* __restrict__ bias, float* __restrict__ C, int Nc) {
  __shared__ __align__(16) float As[16][68];  // [k][m], pad 68: float4-aligned, bank-shifted
  __shared__ __align__(16) float Bs[16][64];  // [k][n]
  const int t = threadIdx.x;
  const int tx = t & 15, ty = t >> 4;
  const int bx = blockIdx.x, by = blockIdx.y;
  const int am = t >> 2, ak = (t & 3) << 2;   // A loader: one float4 per thread
  const int bk = t >> 4, bn = (t & 15) << 2;  // B loader: one float4 per thread
  const float* Aptr = A + (by * 64 + am) * KDIM + ak;
  const float* Bbase = B + bx * 64 + bn;

  float acc[4][4];
#pragma unroll
  for (int i = 0; i < 4; i++)
#pragma unroll
    for (int j = 0; j < 4; j++) acc[i][j] = 0.f;

  for (int k0 = 0; k0 < KDIM; k0 += 16) {
    float4 a = *(const float4*)(Aptr + k0);
    As[ak + 0][am] = a.x;
    As[ak + 1][am] = a.y;
    As[ak + 2][am] = a.z;
    As[ak + 3][am] = a.w;
    *(float4*)&Bs[bk][bn] = *(const float4*)(Bbase + (k0 + bk) * Nc);
    __syncthreads();
#pragma unroll
    for (int k = 0; k < 16; k++) {
      float4 ra = *(const float4*)&As[k][ty << 2];
      float4 rb = *(const float4*)&Bs[k][tx << 2];
      float ar[4] = {ra.x, ra.y, ra.z, ra.w};
      float br[4] = {rb.x, rb.y, rb.z, rb.w};
#pragma unroll
      for (int i = 0; i < 4; i++)
#pragma unroll
        for (int j = 0; j < 4; j++) acc[i][j] += ar[i] * br[j];
    }
    __syncthreads();
  }

  const int row = by * 64 + (ty << 2);
  const int col = bx * 64 + (tx << 2);
  float4 bv = *(const float4*)&bias[col];
#pragma unroll
  for (int i = 0; i < 4; i++) {
    float4 o;
    o.x = acc[i][0] + bv.x;
    o.y = acc[i][1] + bv.y;
    o.z = acc[i][2] + bv.z;
    o.w = acc[i][3] + bv.w;
    *(float4*)&C[(row + i) * Nc + col] = o;
  }
}

// ---------------------------------------------------------------------------
// pe_proj[h][n] = pe[n,:] @ Wpe[:,h] + bpe[h]
// ---------------------------------------------------------------------------
__global__ __launch_bounds__(256) void pe_proj_kernel(
    const float* __restrict__ pe, const float* __restrict__ Wpe,
    const float* __restrict__ bpe) {
  const int n = blockIdx.x * blockDim.x + threadIdx.x;
  if (n >= NTOK) return;
  float pr[16];
#pragma unroll
  for (int i = 0; i < 4; i++) {
    float4 v = *(const float4*)&pe[n * 16 + i * 4];
    pr[i * 4 + 0] = v.x;
    pr[i * 4 + 1] = v.y;
    pr[i * 4 + 2] = v.z;
    pr[i * 4 + 3] = v.w;
  }
#pragma unroll
  for (int h = 0; h < NHEAD; h++) {
    float s = __ldg(&bpe[h]);
#pragma unroll
    for (int d = 0; d < 16; d++) s += pr[d] * __ldg(&Wpe[d * NHEAD + h]);
    g_pe[h * NTOK + n] = s;
  }
}

// ---------------------------------------------------------------------------
// Flash attention per head. 64 query rows per block, 64-key tiles.
// Bias trick: softmax(scale*qk + pe_i - pe_j) == softmax(scale*qk - pe_j).
// Thread map: 256 threads = 64 rows x 4 quad-lanes; quad splits keys (scores)
// and head-dim columns (AV accumulation). Row reductions via quad shuffles.
// ---------------------------------------------------------------------------
__global__ __launch_bounds__(256) void attn_kernel() {
  __shared__ __align__(16) float sK[64][36];  // pad 36: float4-aligned, bank-shift 4
  __shared__ __align__(16) float sV[64][36];
  __shared__ __align__(16) float sP[64][68];
  __shared__ float sPe[64];

  const int h = blockIdx.y;
  const int q0 = blockIdx.x << 6;
  const int t = threadIdx.x;
  const int r = t >> 2;  // query row within tile
  const int g = t & 3;   // quad lane

  // Load this row's query, prescaled, into registers (32 floats)
  float4 q4[8];
  const float4* qrow = (const float4*)(g_qkv + (q0 + r) * 768 + h * HEADD);
#pragma unroll
  for (int i = 0; i < 8; i++) {
    float4 v = qrow[i];
    v.x *= SCALE; v.y *= SCALE; v.z *= SCALE; v.w *= SCALE;
    q4[i] = v;
  }

  float m = -1e30f, l = 0.f;
  float acc[8];
#pragma unroll
  for (int i = 0; i < 8; i++) acc[i] = 0.f;

  for (int k0 = 0; k0 < NTOK; k0 += 64) {
    // Load K and V tiles (64 x 32 floats each), float4-vectorized
#pragma unroll
    for (int e = t; e < 512; e += 256) {
      const int row = e >> 3, dq = e & 7;
      const float* base = g_qkv + (k0 + row) * 768 + h * HEADD;
      ((float4*)sK[row])[dq] = ((const float4*)(base + 256))[dq];
      ((float4*)sV[row])[dq] = ((const float4*)(base + 512))[dq];
    }
    if (t < 64) sPe[t] = g_pe[h * NTOK + k0 + t];
    __syncthreads();

    // Scores for this row's 16-key slice
    float sc[16];
    float mx = -1e30f;
#pragma unroll
    for (int jj = 0; jj < 16; jj++) {
      const int j = (g << 4) + jj;
      const float4* kr = (const float4*)sK[j];
      float s = 0.f;
#pragma unroll
      for (int i = 0; i < 8; i++) {
        float4 kk = kr[i];
        s += q4[i].x * kk.x + q4[i].y * kk.y + q4[i].z * kk.z + q4[i].w * kk.w;
      }
      s -= sPe[j];
      sc[jj] = s;
      mx = fmaxf(mx, s);
    }
    // Row max over quad
    mx = fmaxf(mx, __shfl_xor_sync(0xffffffffu, mx, 1));
    mx = fmaxf(mx, __shfl_xor_sync(0xffffffffu, mx, 2));
    const float m_new = fmaxf(m, mx);

    float psum = 0.f;
#pragma unroll
    for (int jj = 0; jj < 16; jj++) {
      float p = __expf(sc[jj] - m_new);
      sP[r][(g << 4) + jj] = p;
      psum += p;
    }
    psum += __shfl_xor_sync(0xffffffffu, psum, 1);
    psum += __shfl_xor_sync(0xffffffffu, psum, 2);

    const float alpha = __expf(m - m_new);
    l = l * alpha + psum;
    m = m_new;
#pragma unroll
    for (int i = 0; i < 8; i++) acc[i] *= alpha;

    __syncwarp();  // sP row written by this warp's quads, read across quads below

    // acc[d] += sum_j P[r][j] * V[j][d], this thread owns 8 d-columns
#pragma unroll 8
    for (int j = 0; j < 64; j++) {
      const float p = sP[r][j];
      const float4* vr = (const float4*)sV[j];
      float4 va = vr[(g << 1)];
      float4 vb = vr[(g << 1) + 1];
      acc[0] += p * va.x; acc[1] += p * va.y; acc[2] += p * va.z; acc[3] += p * va.w;
      acc[4] += p * vb.x; acc[5] += p * vb.y; acc[6] += p * vb.z; acc[7] += p * vb.w;
    }
    __syncthreads();  // orders sP reads / K,V reuse before next tile's writes
  }

  const float inv = 1.f / l;
  float* o = g_att + (q0 + r) * DMODEL + h * HEADD + (g << 3);
  float4 oa = {acc[0] * inv, acc[1] * inv, acc[2] * inv, acc[3] * inv};
  float4 ob = {acc[4] * inv, acc[5] * inv, acc[6] * inv, acc[7] * inv};
  ((float4*)o)[0] = oa;
  ((float4*)o)[1] = ob;
}

// ---------------------------------------------------------------------------
extern "C" void kernel_launch(void* const* d_in, const int* in_sizes, int n_in,
                              void* d_out, int out_size) {
  const float* x    = (const float*)d_in[0];
  const float* pe   = (const float*)d_in[1];
  const float* Wqkv = (const float*)d_in[2];
  const float* bqkv = (const float*)d_in[3];
  const float* Wpe  = (const float*)d_in[4];
  const float* bpe  = (const float*)d_in[5];
  const float* Wout = (const float*)d_in[6];
  const float* bout = (const float*)d_in[7];
  float* out = (float*)d_out;

  void *p_qkv = nullptr, *p_att = nullptr;
  cudaGetSymbolAddress(&p_qkv, g_qkv);
  cudaGetSymbolAddress(&p_att, g_att);

  // 1) QKV projection: [4096,256] @ [256,768] + b
  gemm_bias_kernel<<<dim3(12, 64), 256>>>(x, Wqkv, bqkv, (float*)p_qkv, 768);
  // 2) PE projection: [4096,16] @ [16,8] + b  -> [h][n]
  pe_proj_kernel<<<16, 256>>>(pe, Wpe, bpe);
  // 3) Flash attention per head with key-side PE bias
  attn_kernel<<<dim3(64, 8), 256>>>();
  // 4) Output projection: [4096,256] @ [256,256] + b
  gemm_bias_kernel<<<dim3(4, 64), 256>>>((const float*)p_att, Wout, bout, out, 256);
}

// round 2
// speedup vs baseline: 3.4061x; 3.4061x over previous
#include <cuda_runtime.h>

#define NTOK 4096
#define DMODEL 256
#define NHEAD 8
#define HEADD 32
#define KDIM 256
#define SCALE 0.17677669529663689f

typedef unsigned long long u64;

// Scratch (device globals — no allocation allowed in kernel_launch)
__device__ float g_qkv[NTOK * 3 * DMODEL];   // [n][c*256 + h*32 + d], c in {q,k,v}
__device__ float g_pe[NHEAD * NTOK];         // [h][n] = pe @ Wpe + bpe
__device__ float g_att[NTOK * DMODEL];       // [n][h*32+d]

// ---------------- packed f32x2 helpers (sm_103a FFMA2 path) ----------------
__device__ __forceinline__ u64 pack2(float lo, float hi) {
  u64 r;
  asm("mov.b64 %0, {%1, %2};" : "=l"(r) : "r"(__float_as_uint(lo)), "r"(__float_as_uint(hi)));
  return r;
}
__device__ __forceinline__ u64 dup2(float v) { return pack2(v, v); }
__device__ __forceinline__ float2 unpack2(u64 v) {
  unsigned lo, hi;
  asm("mov.b64 {%0, %1}, %2;" : "=r"(lo), "=r"(hi) : "l"(v));
  return make_float2(__uint_as_float(lo), __uint_as_float(hi));
}
__device__ __forceinline__ u64 ffma2(u64 a, u64 b, u64 c) {
  u64 d;
  asm("fma.rn.f32x2 %0, %1, %2, %3;" : "=l"(d) : "l"(a), "l"(b), "l"(c));
  return d;
}
__device__ __forceinline__ u64 fmul2(u64 a, u64 b) {
  u64 d;
  asm("mul.rn.f32x2 %0, %1, %2;" : "=l"(d) : "l"(a), "l"(b));
  return d;
}
__device__ __forceinline__ u64 fadd2(u64 a, u64 b) {
  u64 d;
  asm("add.rn.f32x2 %0, %1, %2;" : "=l"(d) : "l"(a), "l"(b));
  return d;
}

// ---------------------------------------------------------------------------
// Tiled SGEMM: C[M,Nc] = A[M,256] @ B[256,Nc] + bias[Nc]
// 64x64 tile, BK=16, 256 threads, 4x4 microtile per thread, FFMA2 inner loop.
// ---------------------------------------------------------------------------
__global__ __launch_bounds__(256) void gemm_bias_kernel(
    const float* __restrict__ A, const float* __restrict__ B,
    const float* __restrict__ bias, float* __restrict__ C, int Nc) {
  __shared__ __align__(16) float As[16][68];  // [k][m]
  __shared__ __align__(16) float Bs[16][64];  // [k][n]
  const int t = threadIdx.x;
  const int tx = t & 15, ty = t >> 4;
  const int bx = blockIdx.x, by = blockIdx.y;
  const int am = t >> 2, ak = (t & 3) << 2;
  const int bk = t >> 4, bn = (t & 15) << 2;
  const float* Aptr = A + (by * 64 + am) * KDIM + ak;
  const float* Bbase = B + bx * 64 + bn;

  u64 acc[4][2];
#pragma unroll
  for (int i = 0; i < 4; i++) { acc[i][0] = 0ull; acc[i][1] = 0ull; }

  for (int k0 = 0; k0 < KDIM; k0 += 16) {
    float4 a = *(const float4*)(Aptr + k0);
    As[ak + 0][am] = a.x;
    As[ak + 1][am] = a.y;
    As[ak + 2][am] = a.z;
    As[ak + 3][am] = a.w;
    *(float4*)&Bs[bk][bn] = *(const float4*)(Bbase + (k0 + bk) * Nc);
    __syncthreads();
#pragma unroll
    for (int k = 0; k < 16; k++) {
      float4 ra = *(const float4*)&As[k][ty << 2];
      ulonglong2 rb = *(const ulonglong2*)&Bs[k][tx << 2];
      u64 a0 = dup2(ra.x), a1 = dup2(ra.y), a2 = dup2(ra.z), a3 = dup2(ra.w);
      acc[0][0] = ffma2(a0, rb.x, acc[0][0]); acc[0][1] = ffma2(a0, rb.y, acc[0][1]);
      acc[1][0] = ffma2(a1, rb.x, acc[1][0]); acc[1][1] = ffma2(a1, rb.y, acc[1][1]);
      acc[2][0] = ffma2(a2, rb.x, acc[2][0]); acc[2][1] = ffma2(a2, rb.y, acc[2][1]);
      acc[3][0] = ffma2(a3, rb.x, acc[3][0]); acc[3][1] = ffma2(a3, rb.y, acc[3][1]);
    }
    __syncthreads();
  }

  const int row = by * 64 + (ty << 2);
  const int col = bx * 64 + (tx << 2);
  float4 bv = *(const float4*)&bias[col];
#pragma unroll
  for (int i = 0; i < 4; i++) {
    float2 lo = unpack2(acc[i][0]);
    float2 hi = unpack2(acc[i][1]);
    float4 o;
    o.x = lo.x + bv.x; o.y = lo.y + bv.y; o.z = hi.x + bv.z; o.w = hi.y + bv.w;
    *(float4*)&C[(row + i) * Nc + col] = o;
  }
}

// ---------------------------------------------------------------------------
// pe_proj[h][n] = pe[n,:] @ Wpe[:,h] + bpe[h]
// ---------------------------------------------------------------------------
__global__ __launch_bounds__(256) void pe_proj_kernel(
    const float* __restrict__ pe, const float* __restrict__ Wpe,
    const float* __restrict__ bpe) {
  const int n = blockIdx.x * blockDim.x + threadIdx.x;
  if (n >= NTOK) return;
  float pr[16];
#pragma unroll
  for (int i = 0; i < 4; i++) {
    float4 v = *(const float4*)&pe[n * 16 + i * 4];
    pr[i * 4 + 0] = v.x; pr[i * 4 + 1] = v.y; pr[i * 4 + 2] = v.z; pr[i * 4 + 3] = v.w;
  }
#pragma unroll
  for (int h = 0; h < NHEAD; h++) {
    float s = __ldg(&bpe[h]);
#pragma unroll
    for (int d = 0; d < 16; d++) s += pr[d] * __ldg(&Wpe[d * NHEAD + h]);
    g_pe[h * NTOK + n] = s;
  }
}

// ---------------------------------------------------------------------------
// Flash attention, GEMM-style register tiling + FFMA2.
// Block: 256 threads as (tx 0..15, ty 0..15); 64 queries per block, 1 head.
// Score phase: thread owns 4q x 4k microtile; rank-1 updates from transposed
//   sQt/sKt rows (ulonglong2 loads feed FFMA2 directly on the key side).
// Softmax: rows owned by ty-group; reduce over 16 tx lanes via shfl_xor 1,2,4,8.
// PV phase: thread owns 4q x 4d (d = (tx&7)*4), k-range split by tx>>3,
//   merged at the end with shfl_xor(...,8).
// PE trick: softmax(scale*qk + pe_i - pe_j) == softmax(scale*qk - pe_j).
// ---------------------------------------------------------------------------
__global__ __launch_bounds__(256) void attn_kernel() {
  __shared__ __align__(16) float sQt[32][68];  // [k-dim][query], prescaled
  __shared__ __align__(16) float sKt[32][68];  // [k-dim][key]
  __shared__ __align__(16) float sV[64][36];   // [key][d]
  __shared__ __align__(16) float sPt[64][68];  // [key][query]
  __shared__ float sPe[64];

  const int h = blockIdx.y;
  const int q0 = blockIdx.x << 6;
  const int t = threadIdx.x;
  const int tx = t & 15, ty = t >> 4;
  const int txd = tx & 7, txk = tx >> 3;

  // Stage Q transposed + prescaled (once per block)
#pragma unroll
  for (int e = t; e < 512; e += 256) {
    const int tok = e & 63, kq = e >> 6;
    float4 v = *(const float4*)(g_qkv + (q0 + tok) * 768 + h * HEADD + kq * 4);
    sQt[kq * 4 + 0][tok] = v.x * SCALE;
    sQt[kq * 4 + 1][tok] = v.y * SCALE;
    sQt[kq * 4 + 2][tok] = v.z * SCALE;
    sQt[kq * 4 + 3][tok] = v.w * SCALE;
  }

  float m[4], l[4];
  u64 acco[4][2];
#pragma unroll
  for (int i = 0; i < 4; i++) {
    m[i] = -1e30f; l[i] = 0.f; acco[i][0] = 0ull; acco[i][1] = 0ull;
  }

  for (int k0 = 0; k0 < NTOK; k0 += 64) {
    // Stage K transposed + V (token-major)
#pragma unroll
    for (int e = t; e < 512; e += 256) {
      const int tok = e & 63, kq = e >> 6;
      const float* base = g_qkv + (k0 + tok) * 768 + h * HEADD + kq * 4;
      float4 kv = *(const float4*)(base + 256);
      sKt[kq * 4 + 0][tok] = kv.x;
      sKt[kq * 4 + 1][tok] = kv.y;
      sKt[kq * 4 + 2][tok] = kv.z;
      sKt[kq * 4 + 3][tok] = kv.w;
      *(float4*)&sV[tok][kq * 4] = *(const float4*)(base + 512);
    }
    if (t < 64) sPe[t] = g_pe[h * NTOK + k0 + t];
    __syncthreads();

    // ---- Scores: 4q x 4k per thread ----
    u64 acc[4][2];
#pragma unroll
    for (int i = 0; i < 4; i++) { acc[i][0] = 0ull; acc[i][1] = 0ull; }
#pragma unroll
    for (int k = 0; k < 32; k++) {
      float4 qa = *(const float4*)&sQt[k][ty << 2];
      ulonglong2 kb = *(const ulonglong2*)&sKt[k][tx << 2];
      u64 a0 = dup2(qa.x), a1 = dup2(qa.y), a2 = dup2(qa.z), a3 = dup2(qa.w);
      acc[0][0] = ffma2(a0, kb.x, acc[0][0]); acc[0][1] = ffma2(a0, kb.y, acc[0][1]);
      acc[1][0] = ffma2(a1, kb.x, acc[1][0]); acc[1][1] = ffma2(a1, kb.y, acc[1][1]);
      acc[2][0] = ffma2(a2, kb.x, acc[2][0]); acc[2][1] = ffma2(a2, kb.y, acc[2][1]);
      acc[3][0] = ffma2(a3, kb.x, acc[3][0]); acc[3][1] = ffma2(a3, kb.y, acc[3][1]);
    }

    // ---- Online softmax (key-side PE bias) ----
    float4 pev = *(const float4*)&sPe[tx << 2];
    float p[4][4];
#pragma unroll
    for (int i = 0; i < 4; i++) {
      float2 lo = unpack2(acc[i][0]);
      float2 hi = unpack2(acc[i][1]);
      float s0 = lo.x - pev.x, s1 = lo.y - pev.y;
      float s2 = hi.x - pev.z, s3 = hi.y - pev.w;
      float mx = fmaxf(fmaxf(s0, s1), fmaxf(s2, s3));
      mx = fmaxf(mx, __shfl_xor_sync(0xffffffffu, mx, 1));
      mx = fmaxf(mx, __shfl_xor_sync(0xffffffffu, mx, 2));
      mx = fmaxf(mx, __shfl_xor_sync(0xffffffffu, mx, 4));
      mx = fmaxf(mx, __shfl_xor_sync(0xffffffffu, mx, 8));
      const float mn = fmaxf(m[i], mx);
      const float alpha = __expf(m[i] - mn);
      m[i] = mn;
      float p0 = __expf(s0 - mn), p1 = __expf(s1 - mn);
      float p2 = __expf(s2 - mn), p3 = __expf(s3 - mn);
      p[i][0] = p0; p[i][1] = p1; p[i][2] = p2; p[i][3] = p3;
      float ps = p0 + p1 + p2 + p3;
      ps += __shfl_xor_sync(0xffffffffu, ps, 1);
      ps += __shfl_xor_sync(0xffffffffu, ps, 2);
      ps += __shfl_xor_sync(0xffffffffu, ps, 4);
      ps += __shfl_xor_sync(0xffffffffu, ps, 8);
      l[i] = l[i] * alpha + ps;
      u64 ad = dup2(alpha);
      acco[i][0] = fmul2(acco[i][0], ad);
      acco[i][1] = fmul2(acco[i][1], ad);
    }

    // P transposed to smem: row = key, col = query (float4 over the 4 q rows)
#pragma unroll
    for (int c = 0; c < 4; c++) {
      float4 pc = make_float4(p[0][c], p[1][c], p[2][c], p[3][c]);
      *(float4*)&sPt[(tx << 2) + c][ty << 2] = pc;
    }
    __syncthreads();

    // ---- PV: 4q x 4d per thread, k split across txk ----
#pragma unroll
    for (int kk = 0; kk < 32; kk++) {
      const int k = (txk << 5) + kk;
      float4 pa = *(const float4*)&sPt[k][ty << 2];
      ulonglong2 vb = *(const ulonglong2*)&sV[k][txd << 2];
      u64 a0 = dup2(pa.x), a1 = dup2(pa.y), a2 = dup2(pa.z), a3 = dup2(pa.w);
      acco[0][0] = ffma2(a0, vb.x, acco[0][0]); acco[0][1] = ffma2(a0, vb.y, acco[0][1]);
      acco[1][0] = ffma2(a1, vb.x, acco[1][0]); acco[1][1] = ffma2(a1, vb.y, acco[1][1]);
      acco[2][0] = ffma2(a2, vb.x, acco[2][0]); acco[2][1] = ffma2(a2, vb.y, acco[2][1]);
      acco[3][0] = ffma2(a3, vb.x, acco[3][0]); acco[3][1] = ffma2(a3, vb.y, acco[3][1]);
    }
    __syncthreads();  // protect sKt/sV/sPt before next tile's staging
  }

  // Merge the two k-halves (partner differs only in txk)
#pragma unroll
  for (int i = 0; i < 4; i++) {
    acco[i][0] = fadd2(acco[i][0], __shfl_xor_sync(0xffffffffu, acco[i][0], 8));
    acco[i][1] = fadd2(acco[i][1], __shfl_xor_sync(0xffffffffu, acco[i][1], 8));
  }

  if (txk == 0) {
#pragma unroll
    for (int i = 0; i < 4; i++) {
      const float inv = 1.f / l[i];
      float2 lo = unpack2(acco[i][0]);
      float2 hi = unpack2(acco[i][1]);
      float4 o = make_float4(lo.x * inv, lo.y * inv, hi.x * inv, hi.y * inv);
      *(float4*)&g_att[(q0 + (ty << 2) + i) * DMODEL + h * HEADD + (txd << 2)] = o;
    }
  }
}

// ---------------------------------------------------------------------------
extern "C" void kernel_launch(void* const* d_in, const int* in_sizes, int n_in,
                              void* d_out, int out_size) {
  const float* x    = (const float*)d_in[0];
  const float* pe   = (const float*)d_in[1];
  const float* Wqkv = (const float*)d_in[2];
  const float* bqkv = (const float*)d_in[3];
  const float* Wpe  = (const float*)d_in[4];
  const float* bpe  = (const float*)d_in[5];
  const float* Wout = (const float*)d_in[6];
  const float* bout = (const float*)d_in[7];
  float* out = (float*)d_out;

  void *p_qkv = nullptr, *p_att = nullptr;
  cudaGetSymbolAddress(&p_qkv, g_qkv);
  cudaGetSymbolAddress(&p_att, g_att);

  gemm_bias_kernel<<<dim3(12, 64), 256>>>(x, Wqkv, bqkv, (float*)p_qkv, 768);
  pe_proj_kernel<<<16, 256>>>(pe, Wpe, bpe);
  attn_kernel<<<dim3(64, 8), 256>>>();
  gemm_bias_kernel<<<dim3(4, 64), 256>>>((const float*)p_att, Wout, bout, out, 256);
}

// round 5
// speedup vs baseline: 17.3538x; 5.0949x over previous
#include <cuda_runtime.h>
#include <cuda_bf16.h>

#define NTOK 4096
#define DMODEL 256
#define NHEAD 8
#define HEADD 32
#define KDIM 256
#define SCALE 0.17677669529663689f

typedef unsigned long long u64;
typedef unsigned int u32;

// Scratch (device globals — no allocation allowed)
__device__ float g_pe[NHEAD * NTOK];           // [h][n]
__device__ float g_att[NTOK * DMODEL];         // attention output fp32
__device__ __nv_bfloat16 g_qb[NTOK * DMODEL];  // Q bf16 [n][h*32+d]
__device__ __nv_bfloat16 g_kb[NTOK * DMODEL];  // K bf16 [n][h*32+d]
__device__ __nv_bfloat16 g_vb[NTOK * DMODEL];  // V bf16 [n][h*32+d]

// ---------------- packed f32x2 helpers (FFMA2) ----------------
__device__ __forceinline__ u64 pack2(float lo, float hi) {
  u64 r;
  asm("mov.b64 %0, {%1, %2};" : "=l"(r) : "r"(__float_as_uint(lo)), "r"(__float_as_uint(hi)));
  return r;
}
__device__ __forceinline__ u64 dup2(float v) { return pack2(v, v); }
__device__ __forceinline__ float2 unpack2(u64 v) {
  unsigned lo, hi;
  asm("mov.b64 {%0, %1}, %2;" : "=r"(lo), "=r"(hi) : "l"(v));
  return make_float2(__uint_as_float(lo), __uint_as_float(hi));
}
__device__ __forceinline__ u64 ffma2(u64 a, u64 b, u64 c) {
  u64 d;
  asm("fma.rn.f32x2 %0, %1, %2, %3;" : "=l"(d) : "l"(a), "l"(b), "l"(c));
  return d;
}

// ---------------- mma.sync / ldmatrix helpers (family-common PTX) ----------
__device__ __forceinline__ u32 smem_u32(const void* p) {
  u32 a;
  asm("{ .reg .u64 t; cvta.to.shared.u64 t, %1; cvt.u32.u64 %0, t; }" : "=r"(a) : "l"(p));
  return a;
}
#define LDSM4(r, addr)                                                        \
  asm volatile("ldmatrix.sync.aligned.m8n8.x4.shared.b16 {%0,%1,%2,%3}, [%4];"\
               : "=r"((r)[0]), "=r"((r)[1]), "=r"((r)[2]), "=r"((r)[3])       \
               : "r"(addr))
#define LDSM4T(r, addr)                                                       \
  asm volatile(                                                               \
      "ldmatrix.sync.aligned.m8n8.x4.trans.shared.b16 {%0,%1,%2,%3}, [%4];"   \
      : "=r"((r)[0]), "=r"((r)[1]), "=r"((r)[2]), "=r"((r)[3])                \
      : "r"(addr))
#define MMA16816(d, a, b0, b1)                                                \
  asm volatile(                                                               \
      "mma.sync.aligned.m16n8k16.row.col.f32.bf16.bf16.f32 "                  \
      "{%0,%1,%2,%3}, {%4,%5,%6,%7}, {%8,%9}, {%0,%1,%2,%3};"                 \
      : "+f"((d)[0]), "+f"((d)[1]), "+f"((d)[2]), "+f"((d)[3])                \
      : "r"((a)[0]), "r"((a)[1]), "r"((a)[2]), "r"((a)[3]), "r"(b0), "r"(b1))

// ---------------------------------------------------------------------------
// QKV GEMM: [4096,256] @ [256,768] + b  ->  bf16 q/k/v row-major
// ---------------------------------------------------------------------------
__global__ __launch_bounds__(256) void gemm_qkv_kernel(
    const float* __restrict__ A, const float* __restrict__ B,
    const float* __restrict__ bias) {
  __shared__ __align__(16) float As[16][68];
  __shared__ __align__(16) float Bs[16][64];
  const int t = threadIdx.x;
  const int tx = t & 15, ty = t >> 4;
  const int bx = blockIdx.x, by = blockIdx.y;
  const int am = t >> 2, ak = (t & 3) << 2;
  const int bk = t >> 4, bn = (t & 15) << 2;
  const float* Aptr = A + (by * 64 + am) * KDIM + ak;
  const float* Bbase = B + bx * 64 + bn;

  u64 acc[4][2];
#pragma unroll
  for (int i = 0; i < 4; i++) { acc[i][0] = 0ull; acc[i][1] = 0ull; }

  for (int k0 = 0; k0 < KDIM; k0 += 16) {
    float4 a = *(const float4*)(Aptr + k0);
    As[ak + 0][am] = a.x; As[ak + 1][am] = a.y;
    As[ak + 2][am] = a.z; As[ak + 3][am] = a.w;
    *(float4*)&Bs[bk][bn] = *(const float4*)(Bbase + (k0 + bk) * 768);
    __syncthreads();
#pragma unroll
    for (int k = 0; k < 16; k++) {
      float4 ra = *(const float4*)&As[k][ty << 2];
      ulonglong2 rb = *(const ulonglong2*)&Bs[k][tx << 2];
      u64 a0 = dup2(ra.x), a1 = dup2(ra.y), a2 = dup2(ra.z), a3 = dup2(ra.w);
      acc[0][0] = ffma2(a0, rb.x, acc[0][0]); acc[0][1] = ffma2(a0, rb.y, acc[0][1]);
      acc[1][0] = ffma2(a1, rb.x, acc[1][0]); acc[1][1] = ffma2(a1, rb.y, acc[1][1]);
      acc[2][0] = ffma2(a2, rb.x, acc[2][0]); acc[2][1] = ffma2(a2, rb.y, acc[2][1]);
      acc[3][0] = ffma2(a3, rb.x, acc[3][0]); acc[3][1] = ffma2(a3, rb.y, acc[3][1]);
    }
    __syncthreads();
  }

  const int row = by * 64 + (ty << 2);
  const int col = bx * 64 + (tx << 2);
  float4 bv = *(const float4*)&bias[col];
  const int type = col >> 8;  // uniform per block (256 % 64 == 0)
  const int hd = col & 255;
  __nv_bfloat16* dst = (type == 0) ? g_qb : (type == 1) ? g_kb : g_vb;
#pragma unroll
  for (int i = 0; i < 4; i++) {
    float2 lo = unpack2(acc[i][0]);
    float2 hi = unpack2(acc[i][1]);
    __nv_bfloat162 a = __floats2bfloat162_rn(lo.x + bv.x, lo.y + bv.y);
    __nv_bfloat162 b = __floats2bfloat162_rn(hi.x + bv.z, hi.y + bv.w);
    uint2 pk = make_uint2(*(u32*)&a, *(u32*)&b);
    *(uint2*)(dst + (row + i) * DMODEL + hd) = pk;
  }
}

// ---------------------------------------------------------------------------
// Output GEMM (fp32): C[M,256] = A[M,256] @ B[256,256] + bias
// ---------------------------------------------------------------------------
__global__ __launch_bounds__(256) void gemm_out_kernel(
    const float* __restrict__ A, const float* __restrict__ B,
    const float* __restrict__ bias, float* __restrict__ C) {
  __shared__ __align__(16) float As[16][68];
  __shared__ __align__(16) float Bs[16][64];
  const int t = threadIdx.x;
  const int tx = t & 15, ty = t >> 4;
  const int bx = blockIdx.x, by = blockIdx.y;
  const int am = t >> 2, ak = (t & 3) << 2;
  const int bk = t >> 4, bn = (t & 15) << 2;
  const float* Aptr = A + (by * 64 + am) * KDIM + ak;
  const float* Bbase = B + bx * 64 + bn;

  u64 acc[4][2];
#pragma unroll
  for (int i = 0; i < 4; i++) { acc[i][0] = 0ull; acc[i][1] = 0ull; }

  for (int k0 = 0; k0 < KDIM; k0 += 16) {
    float4 a = *(const float4*)(Aptr + k0);
    As[ak + 0][am] = a.x; As[ak + 1][am] = a.y;
    As[ak + 2][am] = a.z; As[ak + 3][am] = a.w;
    *(float4*)&Bs[bk][bn] = *(const float4*)(Bbase + (k0 + bk) * 256);
    __syncthreads();
#pragma unroll
    for (int k = 0; k < 16; k++) {
      float4 ra = *(const float4*)&As[k][ty << 2];
      ulonglong2 rb = *(const ulonglong2*)&Bs[k][tx << 2];
      u64 a0 = dup2(ra.x), a1 = dup2(ra.y), a2 = dup2(ra.z), a3 = dup2(ra.w);
      acc[0][0] = ffma2(a0, rb.x, acc[0][0]); acc[0][1] = ffma2(a0, rb.y, acc[0][1]);
      acc[1][0] = ffma2(a1, rb.x, acc[1][0]); acc[1][1] = ffma2(a1, rb.y, acc[1][1]);
      acc[2][0] = ffma2(a2, rb.x, acc[2][0]); acc[2][1] = ffma2(a2, rb.y, acc[2][1]);
      acc[3][0] = ffma2(a3, rb.x, acc[3][0]); acc[3][1] = ffma2(a3, rb.y, acc[3][1]);
    }
    __syncthreads();
  }

  const int row = by * 64 + (ty << 2);
  const int col = bx * 64 + (tx << 2);
  float4 bv = *(const float4*)&bias[col];
#pragma unroll
  for (int i = 0; i < 4; i++) {
    float2 lo = unpack2(acc[i][0]);
    float2 hi = unpack2(acc[i][1]);
    float4 o;
    o.x = lo.x + bv.x; o.y = lo.y + bv.y; o.z = hi.x + bv.z; o.w = hi.y + bv.w;
    *(float4*)&C[(row + i) * 256 + col] = o;
  }
}

// ---------------------------------------------------------------------------
// pe_proj[h][n] = pe[n,:] @ Wpe[:,h] + bpe[h]
// ---------------------------------------------------------------------------
__global__ __launch_bounds__(256) void pe_proj_kernel(
    const float* __restrict__ pe, const float* __restrict__ Wpe,
    const float* __restrict__ bpe) {
  const int n = blockIdx.x * blockDim.x + threadIdx.x;
  if (n >= NTOK) return;
  float pr[16];
#pragma unroll
  for (int i = 0; i < 4; i++) {
    float4 v = *(const float4*)&pe[n * 16 + i * 4];
    pr[i * 4 + 0] = v.x; pr[i * 4 + 1] = v.y; pr[i * 4 + 2] = v.z; pr[i * 4 + 3] = v.w;
  }
#pragma unroll
  for (int h = 0; h < NHEAD; h++) {
    float s = __ldg(&bpe[h]);
#pragma unroll
    for (int d = 0; d < 16; d++) s += pr[d] * __ldg(&Wpe[d * NHEAD + h]);
    g_pe[h * NTOK + n] = s;
  }
}

// ---------------------------------------------------------------------------
// mma.sync flash attention. Block = 128 queries x 1 head, 8 warps; each warp
// owns 16 query rows. 64-key tiles. Fixed-max softmax (scores small for this
// problem): p = exp(S*SCALE - pe_j); O accumulates in fp32 regs across tiles,
// normalized once at the end. Score C-fragments reinterpreted as A-fragments
// for PV (bf16x2 pack, zero shuffles). Register prefetch of next K/V tile.
// ---------------------------------------------------------------------------
#define ROWB 40  // padded smem row: 40 bf16 = 80B (16B-aligned, bank-shifted)

__global__ __launch_bounds__(256) void attn_mma_kernel() {
  __shared__ __align__(16) __nv_bfloat16 sQ[128 * ROWB];
  __shared__ __align__(16) __nv_bfloat16 sK[64 * ROWB];
  __shared__ __align__(16) __nv_bfloat16 sV[64 * ROWB];
  __shared__ float sPe[64];

  const int t = threadIdx.x;
  const int w = t >> 5, l = t & 31;
  const int h = blockIdx.y;
  const int q0 = blockIdx.x * 128;

  // ---- stage Q (128 rows x 32 bf16 = 512 uint4) ----
#pragma unroll
  for (int c = t; c < 512; c += 256) {
    const int r = c >> 2, p = c & 3;
    uint4 v = *(const uint4*)(g_qb + (q0 + r) * DMODEL + h * HEADD + p * 8);
    *(uint4*)(sQ + r * ROWB + p * 8) = v;
  }

  // ---- prefetch tile 0 K/V/pe into registers ----
  // t<128: K rows; t>=128: V rows. Each group covers 64 rows x 4 chunks
  // = 256 uint4 -> 2 per thread (rows r and r+32).
  const int u = t & 127, pr_r = u >> 2, pr_p = u & 3;
  uint4 kv_reg0, kv_reg1;
  float pe_reg = 0.f;
  {
    const __nv_bfloat16* src = (t < 128) ? g_kb : g_vb;
    kv_reg0 = *(const uint4*)(src + pr_r * DMODEL + h * HEADD + pr_p * 8);
    kv_reg1 = *(const uint4*)(src + (pr_r + 32) * DMODEL + h * HEADD + pr_p * 8);
    if (t < 64) pe_reg = g_pe[h * NTOK + t];
  }
  __syncthreads();

  // ---- Q fragments (held for whole kernel): 2 k16-chunks x 4 regs ----
  u32 qa[2][4];
  {
    const int qrow = w * 16 + (l & 7) + ((l >> 3) & 1) * 8;
    const int qcol = (l >> 4) * 8;
    u32 qaddr = smem_u32(sQ) + (qrow * ROWB + qcol) * 2;
    LDSM4(qa[0], qaddr);
    LDSM4(qa[1], qaddr + 32);
  }

  float o[4][4];
#pragma unroll
  for (int nd = 0; nd < 4; nd++)
#pragma unroll
    for (int i = 0; i < 4; i++) o[nd][i] = 0.f;
  float lr0 = 0.f, lr1 = 0.f;

  const u32 sKb = smem_u32(sK), sVb = smem_u32(sV);
  const int kl_row = (l & 7);  // within-group row for ldmatrix
  const int kl_g = (l >> 3);   // ldmatrix 8-thread group

  for (int tile = 0; tile < 64; ++tile) {
    // commit prefetched tile to smem (full rows: chunks p and rows r, r+32)
    {
      __nv_bfloat16* dst = (t < 128) ? sK : sV;
      *(uint4*)(dst + pr_r * ROWB + pr_p * 8) = kv_reg0;
      *(uint4*)(dst + (pr_r + 32) * ROWB + pr_p * 8) = kv_reg1;
      if (t < 64) sPe[t] = pe_reg;
    }
    __syncthreads();
    // issue next tile's global loads (latency hidden behind compute)
    if (tile + 1 < 64) {
      const __nv_bfloat16* src = (t < 128) ? g_kb : g_vb;
      const int base = (tile + 1) * 64;
      kv_reg0 = *(const uint4*)(src + (base + pr_r) * DMODEL + h * HEADD + pr_p * 8);
      kv_reg1 = *(const uint4*)(src + (base + pr_r + 32) * DMODEL + h * HEADD + pr_p * 8);
      if (t < 64) pe_reg = g_pe[h * NTOK + base + t];
    }

    // ---- scores + exp -> P fragments ----
    u32 pa[4][4];  // A-fragments for PV, one per k16 chunk of 64 keys
#pragma unroll
    for (int n = 0; n < 8; ++n) {
      u32 kb[4];
      u32 kaddr = sKb + ((n * 8 + kl_row) * ROWB + kl_g * 8) * 2;
      LDSM4(kb, kaddr);
      float c[4] = {0.f, 0.f, 0.f, 0.f};
      MMA16816(c, qa[0], kb[0], kb[1]);
      MMA16816(c, qa[1], kb[2], kb[3]);
      float2 pe2 = *(const float2*)&sPe[n * 8 + ((l & 3) << 1)];
      float e0 = __expf(fmaf(c[0], SCALE, -pe2.x));
      float e1 = __expf(fmaf(c[1], SCALE, -pe2.y));
      float e2 = __expf(fmaf(c[2], SCALE, -pe2.x));
      float e3 = __expf(fmaf(c[3], SCALE, -pe2.y));
      lr0 += e0 + e1;
      lr1 += e2 + e3;
      __nv_bfloat162 p01 = __floats2bfloat162_rn(e0, e1);
      __nv_bfloat162 p23 = __floats2bfloat162_rn(e2, e3);
      pa[n >> 1][(n & 1) * 2 + 0] = *(u32*)&p01;
      pa[n >> 1][(n & 1) * 2 + 1] = *(u32*)&p23;
    }

    // ---- PV: O[16 x 32] += P[16 x 64] @ V[64 x 32] ----
#pragma unroll
    for (int nd = 0; nd < 4; ++nd) {
      u32 vb0[4], vb1[4];
      u32 va0 = sVb + ((kl_g * 8 + kl_row) * ROWB + nd * 8) * 2;         // keys 0-31
      u32 va1 = sVb + (((32 + kl_g * 8) + kl_row) * ROWB + nd * 8) * 2;  // keys 32-63
      LDSM4T(vb0, va0);
      LDSM4T(vb1, va1);
      MMA16816(o[nd], pa[0], vb0[0], vb0[1]);
      MMA16816(o[nd], pa[1], vb0[2], vb0[3]);
      MMA16816(o[nd], pa[2], vb1[0], vb1[1]);
      MMA16816(o[nd], pa[3], vb1[2], vb1[3]);
    }
    __syncthreads();
  }

  // row sums: reduce over the 4 column-lanes (l&3)
  lr0 += __shfl_xor_sync(0xffffffffu, lr0, 1);
  lr0 += __shfl_xor_sync(0xffffffffu, lr0, 2);
  lr1 += __shfl_xor_sync(0xffffffffu, lr1, 1);
  lr1 += __shfl_xor_sync(0xffffffffu, lr1, 2);
  const float inv0 = 1.f / lr0, inv1 = 1.f / lr1;

  const int row0 = q0 + w * 16 + (l >> 2);
  const int col0 = h * HEADD + ((l & 3) << 1);
#pragma unroll
  for (int nd = 0; nd < 4; ++nd) {
    *(float2*)&g_att[row0 * DMODEL + col0 + nd * 8] =
        make_float2(o[nd][0] * inv0, o[nd][1] * inv0);
    *(float2*)&g_att[(row0 + 8) * DMODEL + col0 + nd * 8] =
        make_float2(o[nd][2] * inv1, o[nd][3] * inv1);
  }
}

// ---------------------------------------------------------------------------
extern "C" void kernel_launch(void* const* d_in, const int* in_sizes, int n_in,
                              void* d_out, int out_size) {
  const float* x    = (const float*)d_in[0];
  const float* pe   = (const float*)d_in[1];
  const float* Wqkv = (const float*)d_in[2];
  const float* bqkv = (const float*)d_in[3];
  const float* Wpe  = (const float*)d_in[4];
  const float* bpe  = (const float*)d_in[5];
  const float* Wout = (const float*)d_in[6];
  const float* bout = (const float*)d_in[7];
  float* out = (float*)d_out;

  void* p_att = nullptr;
  cudaGetSymbolAddress(&p_att, g_att);

  gemm_qkv_kernel<<<dim3(12, 64), 256>>>(x, Wqkv, bqkv);
  pe_proj_kernel<<<16, 256>>>(pe, Wpe, bpe);
  attn_mma_kernel<<<dim3(32, 8), 256>>>();
  gemm_out_kernel<<<dim3(4, 64), 256>>>((const float*)p_att, Wout, bout, out);
}

// round 6
// speedup vs baseline: 21.1885x; 1.2210x over previous
#include <cuda_runtime.h>
#include <cuda_bf16.h>

#define NTOK 4096
#define DMODEL 256
#define NHEAD 8
#define HEADD 32
#define KDIM 256
#define SCALE 0.17677669529663689f

typedef unsigned long long u64;
typedef unsigned int u32;

// Scratch (device globals — no allocation allowed)
__device__ float g_pe[NHEAD * NTOK];           // [h][n]
__device__ float g_att[NTOK * DMODEL];         // attention output fp32
__device__ __nv_bfloat16 g_qb[NTOK * DMODEL];  // Q bf16 [n][h*32+d]
__device__ __nv_bfloat16 g_kb[NTOK * DMODEL];  // K bf16 [n][h*32+d]
__device__ __nv_bfloat16 g_vb[NTOK * DMODEL];  // V bf16 [n][h*32+d]

// ---------------- mma.sync / ldmatrix helpers (family-common PTX) ----------
__device__ __forceinline__ u32 smem_u32(const void* p) {
  u32 a;
  asm("{ .reg .u64 t; cvta.to.shared.u64 t, %1; cvt.u32.u64 %0, t; }" : "=r"(a) : "l"(p));
  return a;
}
__device__ __forceinline__ u32 tf32cvt(float f) {
  u32 r;
  asm("cvt.rna.tf32.f32 %0, %1;" : "=r"(r) : "f"(f));
  return r;
}
#define LDSM4(r, addr)                                                        \
  asm volatile("ldmatrix.sync.aligned.m8n8.x4.shared.b16 {%0,%1,%2,%3}, [%4];"\
               : "=r"((r)[0]), "=r"((r)[1]), "=r"((r)[2]), "=r"((r)[3])       \
               : "r"(addr))
#define LDSM4T(r, addr)                                                       \
  asm volatile(                                                               \
      "ldmatrix.sync.aligned.m8n8.x4.trans.shared.b16 {%0,%1,%2,%3}, [%4];"   \
      : "=r"((r)[0]), "=r"((r)[1]), "=r"((r)[2]), "=r"((r)[3])                \
      : "r"(addr))
#define MMA16816(d, a, b0, b1)                                                \
  asm volatile(                                                               \
      "mma.sync.aligned.m16n8k16.row.col.f32.bf16.bf16.f32 "                  \
      "{%0,%1,%2,%3}, {%4,%5,%6,%7}, {%8,%9}, {%0,%1,%2,%3};"                 \
      : "+f"((d)[0]), "+f"((d)[1]), "+f"((d)[2]), "+f"((d)[3])                \
      : "r"((a)[0]), "r"((a)[1]), "r"((a)[2]), "r"((a)[3]), "r"(b0), "r"(b1))
#define MMATF32(d, a, b)                                                      \
  asm volatile(                                                               \
      "mma.sync.aligned.m16n8k8.row.col.f32.tf32.tf32.f32 "                   \
      "{%0,%1,%2,%3}, {%4,%5,%6,%7}, {%8,%9}, {%0,%1,%2,%3};"                 \
      : "+f"((d)[0]), "+f"((d)[1]), "+f"((d)[2]), "+f"((d)[3])                \
      : "r"((a)[0]), "r"((a)[1]), "r"((a)[2]), "r"((a)[3]),                   \
        "r"((b)[0]), "r"((b)[1]))

// ---------------------------------------------------------------------------
// tf32 tensor-core GEMM: C[M,Nc] = A[M,256] @ B[256,Nc] + bias.
// Block 128x64 tile, 8 warps (4m x 2n), warp 32x32, k-step 16.
// QKV=1: writes bf16 into g_qb/g_kb/g_vb (col/256 selects); QKV=0: fp32 C.
// Fragment gathers are scalar LDS matching PTX m16n8k8 tf32 layout:
//   A: rows l/4, l/4+8; cols l%4, l%4+4.  B: rows l%4, l%4+4; col l/4.
// ---------------------------------------------------------------------------
template <int QKV>
__global__ __launch_bounds__(256) void gemm_tf32_kernel(
    const float* __restrict__ A, const float* __restrict__ B,
    const float* __restrict__ bias, float* __restrict__ C, int Nc) {
  __shared__ u32 As[16][132];  // [k][m], pad 132 (2-way staging conflicts only)
  __shared__ u32 Bs[16][68];   // [k][n]
  const int t = threadIdx.x;
  const int w = t >> 5, l = t & 31;
  const int wm = w & 3, wn = w >> 2;
  const int m0 = wm * 32, n0 = wn * 32;
  const int lk = l & 3, lm = l >> 2;
  const int bx = blockIdx.x, by = blockIdx.y;

  float c[2][4][4];
#pragma unroll
  for (int mt = 0; mt < 2; mt++)
#pragma unroll
    for (int nt = 0; nt < 4; nt++)
#pragma unroll
      for (int i = 0; i < 4; i++) c[mt][nt][i] = 0.f;

  const int ar = t >> 2, ac = (t & 3) << 2;   // A stager: row, k-chunk
  const int br = t >> 4, bc = (t & 15) << 2;  // B stager: k-row, n-chunk

  for (int k0 = 0; k0 < KDIM; k0 += 16) {
#pragma unroll
    for (int it = 0; it < 2; it++) {
      const float4 v =
          *(const float4*)(A + (by * 128 + ar + it * 64) * KDIM + k0 + ac);
      As[ac + 0][ar + it * 64] = tf32cvt(v.x);
      As[ac + 1][ar + it * 64] = tf32cvt(v.y);
      As[ac + 2][ar + it * 64] = tf32cvt(v.z);
      As[ac + 3][ar + it * 64] = tf32cvt(v.w);
    }
    {
      const float4 v = *(const float4*)(B + (k0 + br) * Nc + bx * 64 + bc);
      Bs[br][bc + 0] = tf32cvt(v.x);
      Bs[br][bc + 1] = tf32cvt(v.y);
      Bs[br][bc + 2] = tf32cvt(v.z);
      Bs[br][bc + 3] = tf32cvt(v.w);
    }
    __syncthreads();
#pragma unroll
    for (int kc = 0; kc < 2; kc++) {
      const int kq = kc * 8;
      u32 a[2][4], b[4][2];
#pragma unroll
      for (int mt = 0; mt < 2; mt++) {
        a[mt][0] = As[kq + lk][m0 + mt * 16 + lm];
        a[mt][1] = As[kq + lk][m0 + mt * 16 + lm + 8];
        a[mt][2] = As[kq + lk + 4][m0 + mt * 16 + lm];
        a[mt][3] = As[kq + lk + 4][m0 + mt * 16 + lm + 8];
      }
#pragma unroll
      for (int nt = 0; nt < 4; nt++) {
        b[nt][0] = Bs[kq + lk][n0 + nt * 8 + lm];
        b[nt][1] = Bs[kq + lk + 4][n0 + nt * 8 + lm];
      }
#pragma unroll
      for (int mt = 0; mt < 2; mt++)
#pragma unroll
        for (int nt = 0; nt < 4; nt++) MMATF32(c[mt][nt], a[mt], b[nt]);
    }
    __syncthreads();
  }

#pragma unroll
  for (int mt = 0; mt < 2; mt++) {
    const int row = by * 128 + m0 + mt * 16 + lm;
#pragma unroll
    for (int nt = 0; nt < 4; nt++) {
      const int col = bx * 64 + n0 + nt * 8 + 2 * lk;
      const float2 bv = *(const float2*)&bias[col];
      const float v00 = c[mt][nt][0] + bv.x, v01 = c[mt][nt][1] + bv.y;
      const float v10 = c[mt][nt][2] + bv.x, v11 = c[mt][nt][3] + bv.y;
      if (QKV) {
        const int type = col >> 8, hd = col & 255;
        __nv_bfloat16* dst = (type == 0) ? g_qb : (type == 1) ? g_kb : g_vb;
        __nv_bfloat162 p0 = __floats2bfloat162_rn(v00, v01);
        __nv_bfloat162 p1 = __floats2bfloat162_rn(v10, v11);
        *(u32*)(dst + row * DMODEL + hd) = *(u32*)&p0;
        *(u32*)(dst + (row + 8) * DMODEL + hd) = *(u32*)&p1;
      } else {
        *(float2*)&C[row * Nc + col] = make_float2(v00, v01);
        *(float2*)&C[(row + 8) * Nc + col] = make_float2(v10, v11);
      }
    }
  }
}

// ---------------------------------------------------------------------------
// pe_proj[h][n] = pe[n,:] @ Wpe[:,h] + bpe[h]
// ---------------------------------------------------------------------------
__global__ __launch_bounds__(256) void pe_proj_kernel(
    const float* __restrict__ pe, const float* __restrict__ Wpe,
    const float* __restrict__ bpe) {
  const int n = blockIdx.x * blockDim.x + threadIdx.x;
  if (n >= NTOK) return;
  float pr[16];
#pragma unroll
  for (int i = 0; i < 4; i++) {
    float4 v = *(const float4*)&pe[n * 16 + i * 4];
    pr[i * 4 + 0] = v.x; pr[i * 4 + 1] = v.y; pr[i * 4 + 2] = v.z; pr[i * 4 + 3] = v.w;
  }
#pragma unroll
  for (int h = 0; h < NHEAD; h++) {
    float s = __ldg(&bpe[h]);
#pragma unroll
    for (int d = 0; d < 16; d++) s += pr[d] * __ldg(&Wpe[d * NHEAD + h]);
    g_pe[h * NTOK + n] = s;
  }
}

// ---------------------------------------------------------------------------
// mma.sync flash attention (validated R5). Block = 128 queries x 1 head,
// 8 warps x 16 query rows. Fixed-max softmax, key-side PE bias, fp32 O regs.
// ---------------------------------------------------------------------------
#define ROWB 40  // padded smem row: 40 bf16 = 80B (16B-aligned, bank-shifted)

__global__ __launch_bounds__(256) void attn_mma_kernel() {
  __shared__ __align__(16) __nv_bfloat16 sQ[128 * ROWB];
  __shared__ __align__(16) __nv_bfloat16 sK[64 * ROWB];
  __shared__ __align__(16) __nv_bfloat16 sV[64 * ROWB];
  __shared__ float sPe[64];

  const int t = threadIdx.x;
  const int w = t >> 5, l = t & 31;
  const int h = blockIdx.y;
  const int q0 = blockIdx.x * 128;

  // ---- stage Q (128 rows x 32 bf16 = 512 uint4) ----
#pragma unroll
  for (int c = t; c < 512; c += 256) {
    const int r = c >> 2, p = c & 3;
    uint4 v = *(const uint4*)(g_qb + (q0 + r) * DMODEL + h * HEADD + p * 8);
    *(uint4*)(sQ + r * ROWB + p * 8) = v;
  }

  // ---- prefetch tile 0 K/V/pe into registers ----
  const int u = t & 127, pr_r = u >> 2, pr_p = u & 3;
  uint4 kv_reg0, kv_reg1;
  float pe_reg = 0.f;
  {
    const __nv_bfloat16* src = (t < 128) ? g_kb : g_vb;
    kv_reg0 = *(const uint4*)(src + pr_r * DMODEL + h * HEADD + pr_p * 8);
    kv_reg1 = *(const uint4*)(src + (pr_r + 32) * DMODEL + h * HEADD + pr_p * 8);
    if (t < 64) pe_reg = g_pe[h * NTOK + t];
  }
  __syncthreads();

  // ---- Q fragments (held for whole kernel) ----
  u32 qa[2][4];
  {
    const int qrow = w * 16 + (l & 7) + ((l >> 3) & 1) * 8;
    const int qcol = (l >> 4) * 8;
    u32 qaddr = smem_u32(sQ) + (qrow * ROWB + qcol) * 2;
    LDSM4(qa[0], qaddr);
    LDSM4(qa[1], qaddr + 32);
  }

  float o[4][4];
#pragma unroll
  for (int nd = 0; nd < 4; nd++)
#pragma unroll
    for (int i = 0; i < 4; i++) o[nd][i] = 0.f;
  float lr0 = 0.f, lr1 = 0.f;

  const u32 sKb = smem_u32(sK), sVb = smem_u32(sV);
  const int kl_row = (l & 7);
  const int kl_g = (l >> 3);

  for (int tile = 0; tile < 64; ++tile) {
    {
      __nv_bfloat16* dst = (t < 128) ? sK : sV;
      *(uint4*)(dst + pr_r * ROWB + pr_p * 8) = kv_reg0;
      *(uint4*)(dst + (pr_r + 32) * ROWB + pr_p * 8) = kv_reg1;
      if (t < 64) sPe[t] = pe_reg;
    }
    __syncthreads();
    if (tile + 1 < 64) {
      const __nv_bfloat16* src = (t < 128) ? g_kb : g_vb;
      const int base = (tile + 1) * 64;
      kv_reg0 = *(const uint4*)(src + (base + pr_r) * DMODEL + h * HEADD + pr_p * 8);
      kv_reg1 = *(const uint4*)(src + (base + pr_r + 32) * DMODEL + h * HEADD + pr_p * 8);
      if (t < 64) pe_reg = g_pe[h * NTOK + base + t];
    }

    // ---- scores + exp -> P fragments ----
    u32 pa[4][4];
#pragma unroll
    for (int n = 0; n < 8; ++n) {
      u32 kb[4];
      u32 kaddr = sKb + ((n * 8 + kl_row) * ROWB + kl_g * 8) * 2;
      LDSM4(kb, kaddr);
      float c[4] = {0.f, 0.f, 0.f, 0.f};
      MMA16816(c, qa[0], kb[0], kb[1]);
      MMA16816(c, qa[1], kb[2], kb[3]);
      float2 pe2 = *(const float2*)&sPe[n * 8 + ((l & 3) << 1)];
      float e0 = __expf(fmaf(c[0], SCALE, -pe2.x));
      float e1 = __expf(fmaf(c[1], SCALE, -pe2.y));
      float e2 = __expf(fmaf(c[2], SCALE, -pe2.x));
      float e3 = __expf(fmaf(c[3], SCALE, -pe2.y));
      lr0 += e0 + e1;
      lr1 += e2 + e3;
      __nv_bfloat162 p01 = __floats2bfloat162_rn(e0, e1);
      __nv_bfloat162 p23 = __floats2bfloat162_rn(e2, e3);
      pa[n >> 1][(n & 1) * 2 + 0] = *(u32*)&p01;
      pa[n >> 1][(n & 1) * 2 + 1] = *(u32*)&p23;
    }

    // ---- PV ----
#pragma unroll
    for (int nd = 0; nd < 4; ++nd) {
      u32 vb0[4], vb1[4];
      u32 va0 = sVb + ((kl_g * 8 + kl_row) * ROWB + nd * 8) * 2;
      u32 va1 = sVb + (((32 + kl_g * 8) + kl_row) * ROWB + nd * 8) * 2;
      LDSM4T(vb0, va0);
      LDSM4T(vb1, va1);
      MMA16816(o[nd], pa[0], vb0[0], vb0[1]);
      MMA16816(o[nd], pa[1], vb0[2], vb0[3]);
      MMA16816(o[nd], pa[2], vb1[0], vb1[1]);
      MMA16816(o[nd], pa[3], vb1[2], vb1[3]);
    }
    __syncthreads();
  }

  lr0 += __shfl_xor_sync(0xffffffffu, lr0, 1);
  lr0 += __shfl_xor_sync(0xffffffffu, lr0, 2);
  lr1 += __shfl_xor_sync(0xffffffffu, lr1, 1);
  lr1 += __shfl_xor_sync(0xffffffffu, lr1, 2);
  const float inv0 = 1.f / lr0, inv1 = 1.f / lr1;

  const int row0 = q0 + w * 16 + (l >> 2);
  const int col0 = h * HEADD + ((l & 3) << 1);
#pragma unroll
  for (int nd = 0; nd < 4; ++nd) {
    *(float2*)&g_att[row0 * DMODEL + col0 + nd * 8] =
        make_float2(o[nd][0] * inv0, o[nd][1] * inv0);
    *(float2*)&g_att[(row0 + 8) * DMODEL + col0 + nd * 8] =
        make_float2(o[nd][2] * inv1, o[nd][3] * inv1);
  }
}

// ---------------------------------------------------------------------------
extern "C" void kernel_launch(void* const* d_in, const int* in_sizes, int n_in,
                              void* d_out, int out_size) {
  const float* x    = (const float*)d_in[0];
  const float* pe   = (const float*)d_in[1];
  const float* Wqkv = (const float*)d_in[2];
  const float* bqkv = (const float*)d_in[3];
  const float* Wpe  = (const float*)d_in[4];
  const float* bpe  = (const float*)d_in[5];
  const float* Wout = (const float*)d_in[6];
  const float* bout = (const float*)d_in[7];
  float* out = (float*)d_out;

  void* p_att = nullptr;
  cudaGetSymbolAddress(&p_att, g_att);

  gemm_tf32_kernel<1><<<dim3(12, 32), 256>>>(x, Wqkv, bqkv, nullptr, 768);
  pe_proj_kernel<<<16, 256>>>(pe, Wpe, bpe);
  attn_mma_kernel<<<dim3(32, 8), 256>>>();
  gemm_tf32_kernel<0><<<dim3(4, 32), 256>>>((const float*)p_att, Wout, bout, out, 256);
}